// round 6
// baseline (speedup 1.0000x reference)
#include <cuda_runtime.h>

// Net_32521492365587 — tiny LSTM ensemble + dense decode, single scalar output.
//
// out = (W1^T·W2)·feat + (W2·b1 + b2)   [no nonlinearity between W1 and W2]
// v = W1^T·W2 and c computed concurrently with the gate phase; one barrier.
//
// R6: pair-split each LSTM unit across two adjacent threads (even: i,g gates;
// odd: f,o gates) + one shuffle exchange -> halves the per-thread load count
// and FMA/MUFU critical chain of the slowest pre-barrier producer.
//
// Thread plan (672 threads, 21 warps):
//   tid   0..199 : gen pairs  (pair p=tid>>1 -> feat[p])
//   tid 200..299 : opp pairs  (pair q -> feat[100+q])
//   tid 320..469 : v partial m in [0,38)  -> s_vv[2i]
//   tid 480..629 : v partial m in [38,75) -> s_vv[2i+1]
//   warp 20      : c = W2.b1+b2 (regs); post-bar final dot -> out

__device__ __forceinline__ float sigmoid_f(float v) {
    return 1.0f / (1.0f + __expf(-v));
}

__device__ __forceinline__ float tanh_f(float v) {
    // tanh(v) = 1 - 2/(e^(2v)+1); EX2 + RCP, branch-free, rel err ~1e-6
    const float e = __expf(2.0f * v);
    return fmaf(-2.0f, __frcp_rn(e + 1.0f), 1.0f);
}

__device__ __forceinline__ float warp_sum(float v) {
    #pragma unroll
    for (int off = 16; off; off >>= 1)
        v += __shfl_xor_sync(0xffffffffu, v, off);
    return v;
}

__global__ __launch_bounds__(672, 1)
void net_kernel(const float* __restrict__ x,
                const float* __restrict__ h0_gen,
                const float* __restrict__ c0_gen,
                const float* __restrict__ W_ih_opp,
                const float* __restrict__ b_ih_opp,
                const float* __restrict__ b_hh_opp,
                const float* __restrict__ W_ih_gen,
                const float* __restrict__ W_hh_gen,
                const float* __restrict__ b_ih_gen,
                const float* __restrict__ b_hh_gen,
                const float* __restrict__ W1,
                const float* __restrict__ b1,
                const float* __restrict__ W2,
                const float* __restrict__ b2,
                float* __restrict__ out)
{
    __shared__ float s_feat[152];
    __shared__ float s_vv[304];    // interleaved: [2i]=v_half0, [2i+1]=v_half1

    const int tid  = threadIdx.x;
    const int warp = tid >> 5;
    const int lane = tid & 31;

    float c_reg = 0.0f;            // live only in warp 20

    if (tid < 200) {
        // ================= gen pair: even=(i,g) odd=(f,o) ====================
        const int p   = tid >> 1;          // unit index 0..99
        const int g   = p / 10;
        const int j   = p - g * 10;
        const bool isA = !(tid & 1);

        const float4 xv0 = reinterpret_cast<const float4*>(x)[0];
        const float4 xv1 = reinterpret_cast<const float4*>(x)[1];
        float2 h2[5];
        const float2* __restrict__ h0p = reinterpret_cast<const float2*>(h0_gen + g * 10);
        #pragma unroll
        for (int k = 0; k < 5; ++k) h2[k] = h0p[k];

        // A: rows +0 (i), +20 (g).  B: rows +10 (f), +30 (o).
        const int base = g * 40 + j + (isA ? 0 : 10);
        float d[2];
        #pragma unroll
        for (int k = 0; k < 2; ++k) {
            const int row = base + k * 20;
            const float4* __restrict__ wi = reinterpret_cast<const float4*>(W_ih_gen + row * 8);
            const float2* __restrict__ wh = reinterpret_cast<const float2*>(W_hh_gen + row * 10);
            float acc = b_ih_gen[row] + b_hh_gen[row];
            const float4 a = wi[0], b = wi[1];
            acc = fmaf(a.x, xv0.x, acc); acc = fmaf(a.y, xv0.y, acc);
            acc = fmaf(a.z, xv0.z, acc); acc = fmaf(a.w, xv0.w, acc);
            acc = fmaf(b.x, xv1.x, acc); acc = fmaf(b.y, xv1.y, acc);
            acc = fmaf(b.z, xv1.z, acc); acc = fmaf(b.w, xv1.w, acc);
            #pragma unroll
            for (int kk = 0; kk < 5; ++kk) {
                const float2 w = wh[kk];
                acc = fmaf(w.x, h2[kk].x, acc);
                acc = fmaf(w.y, h2[kk].y, acc);
            }
            d[k] = acc;
        }

        float u, w;
        if (isA) {
            u = sigmoid_f(d[0]) * tanh_f(d[1]);   // sig(i)*tanh(g)
            w = 0.0f;
        } else {
            u = sigmoid_f(d[0]) * c0_gen[p];      // sig(f)*c0
            w = sigmoid_f(d[1]);                  // sig(o)
        }
        const unsigned m = __activemask();
        const float ru = __shfl_xor_sync(m, u, 1);
        const float rw = __shfl_xor_sync(m, w, 1);
        if (isA) {
            const float c2 = ru + u;              // sig(f)*c0 + sig(i)*tanh(g)
            s_feat[p] = rw * tanh_f(c2);          // sig(o)*tanh(c2)
        }
    } else if (tid < 300) {
        // ================= opp pair: even=(i,g) odd=(o) ======================
        // zero initial state -> f-gate dead, c2 = sig(i)*tanh(g)
        const int q   = (tid - 200) >> 1;         // unit 0..49
        const bool isA = !(tid & 1);

        const float4 xv0 = reinterpret_cast<const float4*>(x)[0];
        const float4 xv1 = reinterpret_cast<const float4*>(x)[1];

        float d0 = 0.f, d1 = 0.f;
        {
            const int r0 = isA ? q : (150 + q);   // A: i-row, B: o-row
            const float4* __restrict__ wv = reinterpret_cast<const float4*>(W_ih_opp + r0 * 8);
            float acc = b_ih_opp[r0] + b_hh_opp[r0];
            const float4 a = wv[0], b = wv[1];
            acc = fmaf(a.x, xv0.x, acc); acc = fmaf(a.y, xv0.y, acc);
            acc = fmaf(a.z, xv0.z, acc); acc = fmaf(a.w, xv0.w, acc);
            acc = fmaf(b.x, xv1.x, acc); acc = fmaf(b.y, xv1.y, acc);
            acc = fmaf(b.z, xv1.z, acc); acc = fmaf(b.w, xv1.w, acc);
            d0 = acc;
        }
        if (isA) {                                // A also does g-row (100+q)
            const int r1 = 100 + q;
            const float4* __restrict__ wv = reinterpret_cast<const float4*>(W_ih_opp + r1 * 8);
            float acc = b_ih_opp[r1] + b_hh_opp[r1];
            const float4 a = wv[0], b = wv[1];
            acc = fmaf(a.x, xv0.x, acc); acc = fmaf(a.y, xv0.y, acc);
            acc = fmaf(a.z, xv0.z, acc); acc = fmaf(a.w, xv0.w, acc);
            acc = fmaf(b.x, xv1.x, acc); acc = fmaf(b.y, xv1.y, acc);
            acc = fmaf(b.z, xv1.z, acc); acc = fmaf(b.w, xv1.w, acc);
            d1 = acc;
        }

        const float w = isA ? 0.0f : sigmoid_f(d0);     // B: sig(o)
        const unsigned m = __activemask();
        const float rw = __shfl_xor_sync(m, w, 1);
        if (isA) {
            const float c2 = sigmoid_f(d0) * tanh_f(d1);
            s_feat[100 + q] = rw * tanh_f(c2);
        }
    } else if (tid >= 320 && tid < 470) {
        // ---- v-half0: sum_{m=0}^{37} W2[m]*W1[m,i], FULL unroll ----
        const int i = tid - 320;
        const float* __restrict__ w1c = W1 + i;
        float acc = 0.0f;
        #pragma unroll
        for (int m = 0; m < 38; ++m)
            acc = fmaf(__ldg(W2 + m), w1c[m * 150], acc);
        s_vv[2 * i] = acc;
    } else if (tid >= 480 && tid < 630) {
        // ---- v-half1: sum_{m=38}^{74} W2[m]*W1[m,i], FULL unroll ----
        const int i = tid - 480;
        const float* __restrict__ w1c = W1 + 38 * 150 + i;
        float acc = 0.0f;
        #pragma unroll
        for (int m = 0; m < 37; ++m)
            acc = fmaf(__ldg(W2 + 38 + m), w1c[m * 150], acc);
        s_vv[2 * i + 1] = acc;
    } else if (warp == 20) {
        // ---- c = W2.b1 + b2, kept in registers ----
        float acc = 0.0f;
        #pragma unroll
        for (int m = lane; m < 75; m += 32)
            acc = fmaf(W2[m], b1[m], acc);
        c_reg = warp_sum(acc) + __ldg(b2);
    }
    __syncthreads();

    // ---- tail: out = sum_i (v0[i]+v1[i])*feat[i] + c   (warp 20) ----
    if (warp == 20) {
        const float2* __restrict__ vv2 = reinterpret_cast<const float2*>(s_vv);
        float acc = 0.0f;
        #pragma unroll
        for (int i = lane; i < 150; i += 32) {
            const float2 vv = vv2[i];
            acc = fmaf(vv.x + vv.y, s_feat[i], acc);
        }
        acc = warp_sum(acc);
        if (lane == 0) out[0] = acc + c_reg;
    }
}

extern "C" void kernel_launch(void* const* d_in, const int* in_sizes, int n_in,
                              void* d_out, int out_size)
{
    const float* x        = (const float*)d_in[0];
    const float* h0_gen   = (const float*)d_in[1];
    const float* c0_gen   = (const float*)d_in[2];
    const float* W_ih_opp = (const float*)d_in[3];
    // d_in[4] = W_hh_opp — unused (zero initial state)
    const float* b_ih_opp = (const float*)d_in[5];
    const float* b_hh_opp = (const float*)d_in[6];
    const float* W_ih_gen = (const float*)d_in[7];
    const float* W_hh_gen = (const float*)d_in[8];
    const float* b_ih_gen = (const float*)d_in[9];
    const float* b_hh_gen = (const float*)d_in[10];
    const float* W1       = (const float*)d_in[11];
    const float* b1       = (const float*)d_in[12];
    const float* W2       = (const float*)d_in[13];
    const float* b2       = (const float*)d_in[14];
    float* out = (float*)d_out;

    net_kernel<<<1, 672>>>(x, h0_gen, c0_gen, W_ih_opp, b_ih_opp, b_hh_opp,
                           W_ih_gen, W_hh_gen, b_ih_gen, b_hh_gen,
                           W1, b1, W2, b2, out);
}

// round 7
// speedup vs baseline: 1.3264x; 1.3264x over previous
#include <cuda_runtime.h>

// Net_32521492365587 — tiny LSTM ensemble + dense decode, single scalar output.
//
// out = (W1^T·W2)·feat + (W2·b1 + b2)   [no nonlinearity between W1 and W2]
// v = W1^T·W2 and c computed concurrently with the gate phase; ONE barrier.
//
// R7: R5 structure, but every role occupies WHOLE warps (no warp carries two
// branch arms -> no divergent serialization of two heavy chains in one warp).
//
// Thread plan (544 threads, 17 warps):
//   warps  0..3  (tid   0..127): gen gate lanes, active tid<100 -> s_feat[0..99]
//   warps  4..5  (tid 128..191): opp gate lanes, active o<50    -> s_feat[100..149]
//   warps  6..10 (tid 192..351): v-half0 (m in [0,38)),  i<150  -> s_vv[2i]
//   warps 11..15 (tid 352..511): v-half1 (m in [38,75)), i<150  -> s_vv[2i+1]
//   warp  16     (tid 512..543): c = W2.b1+b2 (regs); post-bar dot -> out

__device__ __forceinline__ float sigmoid_f(float v) {
    return 1.0f / (1.0f + __expf(-v));
}

__device__ __forceinline__ float tanh_f(float v) {
    // tanh(v) = 1 - 2/(e^(2v)+1); EX2 + RCP, branch-free, rel err ~1e-6
    const float e = __expf(2.0f * v);
    return fmaf(-2.0f, __frcp_rn(e + 1.0f), 1.0f);
}

__device__ __forceinline__ float warp_sum(float v) {
    #pragma unroll
    for (int off = 16; off; off >>= 1)
        v += __shfl_xor_sync(0xffffffffu, v, off);
    return v;
}

__global__ __launch_bounds__(544, 1)
void net_kernel(const float* __restrict__ x,
                const float* __restrict__ h0_gen,
                const float* __restrict__ c0_gen,
                const float* __restrict__ W_ih_opp,
                const float* __restrict__ b_ih_opp,
                const float* __restrict__ b_hh_opp,
                const float* __restrict__ W_ih_gen,
                const float* __restrict__ W_hh_gen,
                const float* __restrict__ b_ih_gen,
                const float* __restrict__ b_hh_gen,
                const float* __restrict__ W1,
                const float* __restrict__ b1,
                const float* __restrict__ W2,
                const float* __restrict__ b2,
                float* __restrict__ out)
{
    __shared__ float s_feat[152];
    __shared__ float s_vv[304];    // interleaved: [2i]=v_half0, [2i+1]=v_half1

    const int tid  = threadIdx.x;
    const int warp = tid >> 5;
    const int lane = tid & 31;

    float c_reg = 0.0f;            // live only in warp 16

    if (warp < 4) {
        // ================= gen lanes (tid 0..99) =============================
        if (tid < 100) {
            const int g = tid / 10;
            const int j = tid - g * 10;

            const float4 xv0 = reinterpret_cast<const float4*>(x)[0];
            const float4 xv1 = reinterpret_cast<const float4*>(x)[1];
            float2 h2[5];
            const float2* __restrict__ h0p = reinterpret_cast<const float2*>(h0_gen + g * 10);
            #pragma unroll
            for (int k = 0; k < 5; ++k) h2[k] = h0p[k];
            const float c0v = c0_gen[tid];

            float gate[4];
            #pragma unroll
            for (int k = 0; k < 4; ++k) {
                const int row = g * 40 + k * 10 + j;
                const float4* __restrict__ wi = reinterpret_cast<const float4*>(W_ih_gen + row * 8);
                const float2* __restrict__ wh = reinterpret_cast<const float2*>(W_hh_gen + row * 10);
                float acc = b_ih_gen[row] + b_hh_gen[row];
                const float4 a = wi[0], b = wi[1];
                acc = fmaf(a.x, xv0.x, acc); acc = fmaf(a.y, xv0.y, acc);
                acc = fmaf(a.z, xv0.z, acc); acc = fmaf(a.w, xv0.w, acc);
                acc = fmaf(b.x, xv1.x, acc); acc = fmaf(b.y, xv1.y, acc);
                acc = fmaf(b.z, xv1.z, acc); acc = fmaf(b.w, xv1.w, acc);
                #pragma unroll
                for (int kk = 0; kk < 5; ++kk) {
                    const float2 w = wh[kk];
                    acc = fmaf(w.x, h2[kk].x, acc);
                    acc = fmaf(w.y, h2[kk].y, acc);
                }
                gate[k] = acc;
            }
            // gate order i,f,g,o
            const float c2 = sigmoid_f(gate[1]) * c0v + sigmoid_f(gate[0]) * tanh_f(gate[2]);
            s_feat[tid] = sigmoid_f(gate[3]) * tanh_f(c2);
        }
    } else if (warp < 6) {
        // ================= opp lanes (o = tid-128, active o<50) ==============
        // zero initial state -> f-gate dead, c2 = sig(i)*tanh(g)
        const int o = tid - 128;
        if (o < 50) {
            const float4 xv0 = reinterpret_cast<const float4*>(x)[0];
            const float4 xv1 = reinterpret_cast<const float4*>(x)[1];
            const int rows[3] = { o, 100 + o, 150 + o };   // i, g, o rows
            float gv[3];
            #pragma unroll
            for (int k = 0; k < 3; ++k) {
                const int row = rows[k];
                const float4* __restrict__ w = reinterpret_cast<const float4*>(W_ih_opp + row * 8);
                float acc = b_ih_opp[row] + b_hh_opp[row];
                const float4 a = w[0], b = w[1];
                acc = fmaf(a.x, xv0.x, acc); acc = fmaf(a.y, xv0.y, acc);
                acc = fmaf(a.z, xv0.z, acc); acc = fmaf(a.w, xv0.w, acc);
                acc = fmaf(b.x, xv1.x, acc); acc = fmaf(b.y, xv1.y, acc);
                acc = fmaf(b.z, xv1.z, acc); acc = fmaf(b.w, xv1.w, acc);
                gv[k] = acc;
            }
            const float c2 = sigmoid_f(gv[0]) * tanh_f(gv[1]);
            s_feat[100 + o] = sigmoid_f(gv[2]) * tanh_f(c2);
        }
    } else if (warp < 11) {
        // ---- v-half0: sum_{m=0}^{37} W2[m]*W1[m,i], FULL unroll ----
        const int i = tid - 192;
        if (i < 150) {
            const float* __restrict__ w1c = W1 + i;
            float acc = 0.0f;
            #pragma unroll
            for (int m = 0; m < 38; ++m)
                acc = fmaf(__ldg(W2 + m), w1c[m * 150], acc);
            s_vv[2 * i] = acc;
        }
    } else if (warp < 16) {
        // ---- v-half1: sum_{m=38}^{74} W2[m]*W1[m,i], FULL unroll ----
        const int i = tid - 352;
        if (i < 150) {
            const float* __restrict__ w1c = W1 + 38 * 150 + i;
            float acc = 0.0f;
            #pragma unroll
            for (int m = 0; m < 37; ++m)
                acc = fmaf(__ldg(W2 + 38 + m), w1c[m * 150], acc);
            s_vv[2 * i + 1] = acc;
        }
    } else {
        // ---- warp 16: c = W2.b1 + b2, kept in registers ----
        float acc = 0.0f;
        #pragma unroll
        for (int m = lane; m < 75; m += 32)
            acc = fmaf(W2[m], b1[m], acc);
        c_reg = warp_sum(acc) + __ldg(b2);
    }
    __syncthreads();

    // ---- tail: out = sum_i (v0[i]+v1[i])*feat[i] + c   (warp 16) ----
    if (warp == 16) {
        const float2* __restrict__ vv2 = reinterpret_cast<const float2*>(s_vv);
        float acc = 0.0f;
        #pragma unroll
        for (int i = lane; i < 150; i += 32) {
            const float2 vv = vv2[i];
            acc = fmaf(vv.x + vv.y, s_feat[i], acc);
        }
        acc = warp_sum(acc);
        if (lane == 0) out[0] = acc + c_reg;
    }
}

extern "C" void kernel_launch(void* const* d_in, const int* in_sizes, int n_in,
                              void* d_out, int out_size)
{
    const float* x        = (const float*)d_in[0];
    const float* h0_gen   = (const float*)d_in[1];
    const float* c0_gen   = (const float*)d_in[2];
    const float* W_ih_opp = (const float*)d_in[3];
    // d_in[4] = W_hh_opp — unused (zero initial state)
    const float* b_ih_opp = (const float*)d_in[5];
    const float* b_hh_opp = (const float*)d_in[6];
    const float* W_ih_gen = (const float*)d_in[7];
    const float* W_hh_gen = (const float*)d_in[8];
    const float* b_ih_gen = (const float*)d_in[9];
    const float* b_hh_gen = (const float*)d_in[10];
    const float* W1       = (const float*)d_in[11];
    const float* b1       = (const float*)d_in[12];
    const float* W2       = (const float*)d_in[13];
    const float* b2       = (const float*)d_in[14];
    float* out = (float*)d_out;

    net_kernel<<<1, 544>>>(x, h0_gen, c0_gen, W_ih_opp, b_ih_opp, b_hh_opp,
                           W_ih_gen, W_hh_gen, b_ih_gen, b_hh_gen,
                           W1, b1, W2, b2, out);
}